// round 10
// baseline (speedup 1.0000x reference)
#include <cuda_runtime.h>

// GradientLayer: 4->256->256->256->256->2 tanh MLP, forward jet propagation of
// (value, d/dx0..d/dx3, d2/dx0^2..d2/dx2^2) = 8 channels per neuron.
// Register-tiled jet-GEMM: thread (m = sample, n = j-group) owns an
// 8ch x 8j accumulator tile of f32x2 pairs; A-frag (state) and B-frag
// (smem-staged W tile) are reused 8x per load, flipping the bottleneck
// from the smem pipe (95% in R4) to the FFMA2 pipe.

#define HDIM 256
#define SAMP 8
#define DIN  4
#define KT   32                    // k rows staged per W tile
#define SROW 2052                  // state floats per sample: 256*8 + 4 pad (bank spread)

__device__ __forceinline__ unsigned long long ffma2(unsigned long long a,
                                                    unsigned long long b,
                                                    unsigned long long c) {
    unsigned long long d;
    asm("fma.rn.f32x2 %0, %1, %2, %3;" : "=l"(d) : "l"(a), "l"(b), "l"(c));
    return d;
}
__device__ __forceinline__ unsigned long long pack2(float lo, float hi) {
    unsigned long long r;
    asm("mov.b64 %0, {%1, %2};" : "=l"(r) : "f"(lo), "f"(hi));
    return r;
}
__device__ __forceinline__ void unpack2(unsigned long long v, float& a, float& b) {
    asm("mov.b64 {%0, %1}, %2;" : "=f"(a), "=f"(b) : "l"(v));
}

__global__ void __launch_bounds__(256, 2)
mlp_jet_kernel(const float* __restrict__ x,
               const float* __restrict__ W0, const float* __restrict__ b0,
               const float* __restrict__ W1, const float* __restrict__ b1,
               const float* __restrict__ W2, const float* __restrict__ b2,
               const float* __restrict__ W3, const float* __restrict__ b3,
               const float* __restrict__ Wo, const float* __restrict__ bo,
               float* __restrict__ out, int B)
{
    extern __shared__ float smem[];
    float* wsm = smem;                    // KT x 256 staged W tile (32 KB)
    float* st  = smem + KT * HDIM;        // state: SAMP x SROW (~64 KB, padded)
    __shared__ float xs[SAMP * DIN];

    const int tid = threadIdx.x;
    const int m   = tid & 7;              // sample within block
    const int n   = tid >> 3;             // j-group: this thread owns j0..j0+7
    const int j0  = n * 8;
    const int s0  = blockIdx.x * SAMP;

    if (tid < SAMP * DIN) {
        int ss = tid / DIN, kk = tid % DIN;
        int gs = s0 + ss;
        xs[tid] = (gs < B) ? x[gs * DIN + kk] : 0.0f;
    }
    __syncthreads();

    // ---- layer 0: 4 -> 256. Input jets: g_i = e_i, h = 0. ----
    {
        float x0 = xs[m * 4 + 0], x1 = xs[m * 4 + 1];
        float x2 = xs[m * 4 + 2], x3 = xs[m * 4 + 3];
        float4 w0a = *(const float4*)(W0 + 0 * HDIM + j0);
        float4 w0b = *(const float4*)(W0 + 0 * HDIM + j0 + 4);
        float4 w1a = *(const float4*)(W0 + 1 * HDIM + j0);
        float4 w1b = *(const float4*)(W0 + 1 * HDIM + j0 + 4);
        float4 w2a = *(const float4*)(W0 + 2 * HDIM + j0);
        float4 w2b = *(const float4*)(W0 + 2 * HDIM + j0 + 4);
        float4 w3a = *(const float4*)(W0 + 3 * HDIM + j0);
        float4 w3b = *(const float4*)(W0 + 3 * HDIM + j0 + 4);
        float4 ba  = *(const float4*)(b0 + j0);
        float4 bb  = *(const float4*)(b0 + j0 + 4);
        const float* wa0 = &w0a.x; const float* wb0 = &w0b.x;
        const float* wa1 = &w1a.x; const float* wb1 = &w1b.x;
        const float* wa2 = &w2a.x; const float* wb2 = &w2b.x;
        const float* wa3 = &w3a.x; const float* wb3 = &w3b.x;
        const float* bap = &ba.x;  const float* bbp = &bb.x;
        #pragma unroll
        for (int jj = 0; jj < 8; jj++) {
            float c0 = (jj < 4) ? wa0[jj & 3] : wb0[jj & 3];
            float c1 = (jj < 4) ? wa1[jj & 3] : wb1[jj & 3];
            float c2 = (jj < 4) ? wa2[jj & 3] : wb2[jj & 3];
            float c3 = (jj < 4) ? wa3[jj & 3] : wb3[jj & 3];
            float bl = (jj < 4) ? bap[jj & 3] : bbp[jj & 3];
            float u = bl + x0 * c0 + x1 * c1 + x2 * c2 + x3 * c3;
            float v = tanhf(u);
            float d = 1.0f - v * v;
            float mm = -2.0f * v * d;
            float4* p = (float4*)&st[m * SROW + (j0 + jj) * 8];
            p[0] = make_float4(v, d * c0, d * c1, d * c2);
            p[1] = make_float4(d * c3, mm * c0 * c0, mm * c1 * c1, mm * c2 * c2);
        }
    }

    // ---- hidden layers 1..3: 256 -> 256 register-tiled jet GEMM ----
    const float* Wlist[3] = { W1, W2, W3 };
    const float* blist[3] = { b1, b2, b3 };
    #pragma unroll 1
    for (int layer = 0; layer < 3; layer++) {
        const float* __restrict__ Wl = Wlist[layer];

        unsigned long long acc0[8], acc1[8], acc2[8], acc3[8];
        #pragma unroll
        for (int jj = 0; jj < 8; jj++) {
            acc0[jj] = 0ull; acc1[jj] = 0ull; acc2[jj] = 0ull; acc3[jj] = 0ull;
        }

        #pragma unroll 1
        for (int t = 0; t < HDIM / KT; t++) {
            __syncthreads();   // prior tile fully consumed / prior state written
            // stage W rows [t*KT, t*KT+KT) : KT*256 floats, coalesced float4
            {
                const float4* src = (const float4*)(Wl + t * KT * HDIM);
                float4* dst = (float4*)wsm;
                #pragma unroll
                for (int i = 0; i < (KT * HDIM / 4) / 256; i++)
                    dst[tid + i * 256] = src[tid + i * 256];
            }
            __syncthreads();

            const float* abase = st + m * SROW + t * KT * 8;
            #pragma unroll 8
            for (int kk = 0; kk < KT; kk++) {
                const ulonglong2* ap = (const ulonglong2*)(abase + kk * 8);
                ulonglong2 a01 = ap[0];   // (v,g0) | (g1,g2)
                ulonglong2 a23 = ap[1];   // (g3,h0) | (h1,h2)
                const float* wr = wsm + kk * HDIM + j0;
                float4 wlo = *(const float4*)wr;
                float4 whi = *(const float4*)(wr + 4);
                unsigned long long ww[8];
                ww[0] = pack2(wlo.x, wlo.x); ww[1] = pack2(wlo.y, wlo.y);
                ww[2] = pack2(wlo.z, wlo.z); ww[3] = pack2(wlo.w, wlo.w);
                ww[4] = pack2(whi.x, whi.x); ww[5] = pack2(whi.y, whi.y);
                ww[6] = pack2(whi.z, whi.z); ww[7] = pack2(whi.w, whi.w);
                #pragma unroll
                for (int jj = 0; jj < 8; jj++) {
                    acc0[jj] = ffma2(a01.x, ww[jj], acc0[jj]);
                    acc1[jj] = ffma2(a01.y, ww[jj], acc1[jj]);
                    acc2[jj] = ffma2(a23.x, ww[jj], acc2[jj]);
                    acc3[jj] = ffma2(a23.y, ww[jj], acc3[jj]);
                }
            }
        }

        float4 bla = *(const float4*)(blist[layer] + j0);
        float4 blb = *(const float4*)(blist[layer] + j0 + 4);
        const float* blap = &bla.x; const float* blbp = &blb.x;

        __syncthreads();   // all reads of current state done before overwrite

        #pragma unroll
        for (int jj = 0; jj < 8; jj++) {
            float uv, g0, g1, g2, g3, h0, h1, h2;
            unpack2(acc0[jj], uv, g0);
            unpack2(acc1[jj], g1, g2);
            unpack2(acc2[jj], g3, h0);
            unpack2(acc3[jj], h1, h2);
            uv += (jj < 4) ? blap[jj & 3] : blbp[jj & 3];
            float v = tanhf(uv);
            float d = 1.0f - v * v;
            float mm = -2.0f * v * d;
            float4* p = (float4*)&st[m * SROW + (j0 + jj) * 8];
            p[0] = make_float4(v, d * g0, d * g1, d * g2);
            p[1] = make_float4(d * g3,
                               d * h0 + mm * g0 * g0,
                               d * h1 + mm * g1 * g1,
                               d * h2 + mm * g2 * g2);
        }
    }
    __syncthreads();

    // ---- output layer 256 -> 2 + divergence epilogue: one warp per sample ----
    const int warp = tid >> 5;
    const int lane = tid & 31;
    const int gs   = s0 + warp;

    float p0[8], p1[8];
    #pragma unroll
    for (int c = 0; c < 8; c++) { p0[c] = 0.0f; p1[c] = 0.0f; }

    #pragma unroll
    for (int t = 0; t < 8; t++) {
        int jj = lane + t * 32;
        float wo0 = Wo[jj * 2 + 0];
        float wo1 = Wo[jj * 2 + 1];
        const float* sp = &st[warp * SROW + jj * 8];
        #pragma unroll
        for (int c = 0; c < 8; c++) {
            float sv = sp[c];
            p0[c] = fmaf(sv, wo0, p0[c]);
            p1[c] = fmaf(sv, wo1, p1[c]);
        }
    }
    #pragma unroll
    for (int off = 16; off > 0; off >>= 1) {
        #pragma unroll
        for (int c = 0; c < 8; c++) {
            p0[c] += __shfl_xor_sync(0xffffffffu, p0[c], off);
            p1[c] += __shfl_xor_sync(0xffffffffu, p1[c], off);
        }
    }

    if (lane == 0 && gs < B) {
        float c   = p0[0] + bo[0];
        float Fi  = p1[0] + bo[1];
        float ct  = p0[4];                      // dc/dx3 (TDIM=3)
        float cg0 = p0[1], cg1 = p0[2], cg2 = p0[3];
        float fg0 = p1[1], fg1 = p1[2], fg2 = p1[3];
        float clap = p0[5] + p0[6] + p0[7];     // trace Hc[:3,:3]
        float flap = p1[5] + p1[6] + p1[7];     // trace HFi[:3,:3]
        float jdiv = -clap
                   - (cg0 * fg0 + cg1 * fg1 + cg2 * fg2 + c * flap)
                   + 0.1f * (cg0 + cg1 + cg2);

        out[gs]                   = c;
        out[B + gs]               = ct;
        out[2 * B + gs * 3 + 0]   = cg0;
        out[2 * B + gs * 3 + 1]   = cg1;
        out[2 * B + gs * 3 + 2]   = cg2;
        out[5 * B + gs]           = Fi;
        out[6 * B + gs * 3 + 0]   = fg0;
        out[6 * B + gs * 3 + 1]   = fg1;
        out[6 * B + gs * 3 + 2]   = fg2;
        out[9 * B + gs]           = flap;
        out[10 * B + gs]          = jdiv;
    }
}

extern "C" void kernel_launch(void* const* d_in, const int* in_sizes, int n_in,
                              void* d_out, int out_size)
{
    const float* x  = (const float*)d_in[0];
    const float* W0 = (const float*)d_in[1];
    const float* b0 = (const float*)d_in[2];
    const float* W1 = (const float*)d_in[3];
    const float* b1 = (const float*)d_in[4];
    const float* W2 = (const float*)d_in[5];
    const float* b2 = (const float*)d_in[6];
    const float* W3 = (const float*)d_in[7];
    const float* b3 = (const float*)d_in[8];
    const float* Wo = (const float*)d_in[9];
    const float* bo = (const float*)d_in[10];
    float* out = (float*)d_out;

    const int B = in_sizes[0] / DIN;
    const int smem = (KT * HDIM + SAMP * SROW) * (int)sizeof(float);  // ~96.8 KB

    cudaFuncSetAttribute(mlp_jet_kernel,
                         cudaFuncAttributeMaxDynamicSharedMemorySize, smem);

    dim3 grid((B + SAMP - 1) / SAMP);
    mlp_jet_kernel<<<grid, 256, smem>>>(x, W0, b0, W1, b1, W2, b2, W3, b3,
                                        Wo, bo, out, B);
}

// round 15
// speedup vs baseline: 1.4188x; 1.4188x over previous
#include <cuda_runtime.h>
#include <cstdint>

// GradientLayer jet-propagation via legacy mma.sync bf16 (sm_80 PTX, runs on
// Blackwell tensor cores without the sm_103a-only tcgen05 path).
// M=128 rows/CTA = 16 samples x 8 jet channels (v, g0..g3, h0..h2).
// Hidden layer: D[128x256] = A[128x256] * W[256x256], A,W split hi/lo bf16,
// 3 products (hh, hl, lh). State kept as bf16 hi/lo in smem between layers.

#define HD   256
#define SPC  16            // samples per CTA -> M = 128
#define KC   32            // k per staged W chunk
#define NCHK 8

// smem byte offsets
#define SH_STRIDE 528u     // state row stride bytes (264 bf16): r*132w = 4r mod 32
#define OFF_SHI   0u
#define OFF_SLO   67584u   // 128*528
#define OFF_B     135168u  // 2 bufs x (hi 20480 + lo 20480)
#define BW_STRIDE 80u      // W-chunk row stride bytes (40 bf16): n*20w pattern
#define BUF_SZ    40960u
#define SMEM_BYTES 217088

__device__ __forceinline__ uint32_t bf2(float lo, float hi) {
    uint32_t r;
    asm("cvt.rn.bf16x2.f32 %0, %1, %2;" : "=r"(r) : "f"(hi), "f"(lo));
    return r;
}
__device__ __forceinline__ float bflo(uint32_t p) { return __uint_as_float(p << 16); }
__device__ __forceinline__ float bfhi(uint32_t p) { return __uint_as_float(p & 0xffff0000u); }

__device__ __forceinline__ void mma16816(float* d, uint32_t a0, uint32_t a1,
                                         uint32_t a2, uint32_t a3,
                                         uint32_t b0, uint32_t b1) {
    asm volatile(
        "mma.sync.aligned.m16n8k16.row.col.f32.bf16.bf16.f32 "
        "{%0,%1,%2,%3}, {%4,%5,%6,%7}, {%8,%9}, {%0,%1,%2,%3};"
        : "+f"(d[0]), "+f"(d[1]), "+f"(d[2]), "+f"(d[3])
        : "r"(a0), "r"(a1), "r"(a2), "r"(a3), "r"(b0), "r"(b1));
}

// pack pair (f0,f1) -> hi bf16x2 + lo bf16x2 (residual split)
__device__ __forceinline__ void split2(float f0, float f1, uint32_t& ph, uint32_t& pl) {
    ph = bf2(f0, f1);
    float l0 = f0 - bflo(ph);
    float l1 = f1 - bfhi(ph);
    pl = bf2(l0, l1);
}

__global__ void __launch_bounds__(512, 1)
jet_mma_kernel(const float* __restrict__ x,
               const float* __restrict__ W0, const float* __restrict__ b0,
               const float* __restrict__ W1, const float* __restrict__ b1,
               const float* __restrict__ W2, const float* __restrict__ b2,
               const float* __restrict__ W3, const float* __restrict__ b3,
               const float* __restrict__ Wo, const float* __restrict__ bo,
               float* __restrict__ out, int B)
{
    extern __shared__ __align__(16) char sm[];
    const int tid  = threadIdx.x;
    const int lane = tid & 31;
    const int w    = tid >> 5;
    const int warpM = w >> 2;            // 0..3 -> rows warpM*32..+31
    const int warpN = w & 3;             // 0..3 -> cols warpN*64..+63
    const int s0   = blockIdx.x * SPC;

    // ---- layer 0: 4->256, write initial jet state (bf16 hi/lo) ----
    {
        const int r  = tid >> 2;          // row 0..127
        const int j0 = (tid & 3) * 64;
        const int s  = r >> 3, ch = r & 7;
        const int gs = s0 + s;
        float x0 = 0.f, x1 = 0.f, x2 = 0.f, x3 = 0.f;
        if (gs < B) {
            x0 = __ldg(x + gs * 4 + 0); x1 = __ldg(x + gs * 4 + 1);
            x2 = __ldg(x + gs * 4 + 2); x3 = __ldg(x + gs * 4 + 3);
        }
        char* shi = sm + OFF_SHI + (uint32_t)r * SH_STRIDE;
        char* slo = sm + OFF_SLO + (uint32_t)r * SH_STRIDE;
        #pragma unroll 4
        for (int i = 0; i < 64; i += 2) {
            float o[2];
            #pragma unroll
            for (int e = 0; e < 2; e++) {
                const int j = j0 + i + e;
                float w0v = __ldg(W0 + j),          w1v = __ldg(W0 + HD + j);
                float w2v = __ldg(W0 + 2 * HD + j), w3v = __ldg(W0 + 3 * HD + j);
                float u = __ldg(b0 + j) + x0 * w0v + x1 * w1v + x2 * w2v + x3 * w3v;
                float v = tanhf(u);
                float d = 1.f - v * v;
                float m = -2.f * v * d;
                float wg = (ch == 1 || ch == 5) ? w0v : (ch == 2 || ch == 6) ? w1v
                         : (ch == 3 || ch == 7) ? w2v : w3v;
                o[e] = (ch == 0) ? v : (ch <= 4) ? d * wg : m * wg * wg;
            }
            uint32_t ph, pl;
            split2(o[0], o[1], ph, pl);
            *(uint32_t*)(shi + (j0 + i) * 2) = ph;
            *(uint32_t*)(slo + (j0 + i) * 2) = pl;
        }
    }
    __syncthreads();

    // ---- hidden layers ----
    const float* Wl[3] = { W1, W2, W3 };
    const float* bl[3] = { b1, b2, b3 };
    const int stg_g = tid >> 8;          // 0/1: k half
    const int stg_n = tid & 255;

    #pragma unroll 1
    for (int layer = 0; layer < 3; layer++) {
        const float* __restrict__ Wc = Wl[layer];

        // stage chunk 0 into buf 0
        {
            const float* wp = Wc + (0 * KC + stg_g * 16) * HD + stg_n;
            float f[16];
            #pragma unroll
            for (int i = 0; i < 16; i++) f[i] = __ldg(wp + i * HD);
            char* bb = sm + OFF_B;
            #pragma unroll
            for (int p = 0; p < 8; p++) {
                uint32_t ph, pl;
                split2(f[2 * p], f[2 * p + 1], ph, pl);
                const uint32_t o = (uint32_t)stg_n * BW_STRIDE + (stg_g * 16 + 2 * p) * 2;
                *(uint32_t*)(bb + o)          = ph;
                *(uint32_t*)(bb + 20480u + o) = pl;
            }
        }
        __syncthreads();

        float acc[2][8][4];
        #pragma unroll
        for (int mt = 0; mt < 2; mt++)
            #pragma unroll
            for (int nt = 0; nt < 8; nt++)
                #pragma unroll
                for (int q = 0; q < 4; q++) acc[mt][nt][q] = 0.f;

        #pragma unroll 1
        for (int t = 0; t < NCHK; t++) {
            const int buf = t & 1;
            // prefetch next chunk's W into registers
            float pf[16];
            if (t + 1 < NCHK) {
                const float* wp = Wc + ((t + 1) * KC + stg_g * 16) * HD + stg_n;
                #pragma unroll
                for (int i = 0; i < 16; i++) pf[i] = __ldg(wp + i * HD);
            }
            // MMA over this chunk
            const char* bb = sm + OFF_B + buf * BUF_SZ;
            #pragma unroll
            for (int ks = 0; ks < 2; ks++) {
                const int kg = t * KC + ks * 16 + 2 * (lane & 3);
                const int kl = ks * 16 + 2 * (lane & 3);
                uint32_t ah[2][4], al[2][4];
                #pragma unroll
                for (int mt = 0; mt < 2; mt++) {
                    const uint32_t r0 = (uint32_t)(warpM * 32 + mt * 16 + (lane >> 2));
                    const char* ph = sm + OFF_SHI + r0 * SH_STRIDE + kg * 2;
                    const char* pl = sm + OFF_SLO + r0 * SH_STRIDE + kg * 2;
                    ah[mt][0] = *(const uint32_t*)(ph);
                    ah[mt][1] = *(const uint32_t*)(ph + 8 * SH_STRIDE);
                    ah[mt][2] = *(const uint32_t*)(ph + 16);
                    ah[mt][3] = *(const uint32_t*)(ph + 8 * SH_STRIDE + 16);
                    al[mt][0] = *(const uint32_t*)(pl);
                    al[mt][1] = *(const uint32_t*)(pl + 8 * SH_STRIDE);
                    al[mt][2] = *(const uint32_t*)(pl + 16);
                    al[mt][3] = *(const uint32_t*)(pl + 8 * SH_STRIDE + 16);
                }
                #pragma unroll
                for (int nt = 0; nt < 8; nt++) {
                    const uint32_t nB = (uint32_t)(warpN * 64 + nt * 8 + (lane >> 2));
                    const char* pb = bb + nB * BW_STRIDE + kl * 2;
                    uint32_t b0h = *(const uint32_t*)(pb);
                    uint32_t b1h = *(const uint32_t*)(pb + 16);
                    uint32_t b0l = *(const uint32_t*)(pb + 20480u);
                    uint32_t b1l = *(const uint32_t*)(pb + 20480u + 16);
                    #pragma unroll
                    for (int mt = 0; mt < 2; mt++) {
                        mma16816(acc[mt][nt], ah[mt][0], ah[mt][1], ah[mt][2], ah[mt][3], b0h, b1h);
                        mma16816(acc[mt][nt], ah[mt][0], ah[mt][1], ah[mt][2], ah[mt][3], b0l, b1l);
                        mma16816(acc[mt][nt], al[mt][0], al[mt][1], al[mt][2], al[mt][3], b0h, b1h);
                    }
                }
            }
            // store prefetched chunk into other buffer
            if (t + 1 < NCHK) {
                char* nb = sm + OFF_B + (buf ^ 1) * BUF_SZ;
                #pragma unroll
                for (int p = 0; p < 8; p++) {
                    uint32_t ph, pl;
                    split2(pf[2 * p], pf[2 * p + 1], ph, pl);
                    const uint32_t o = (uint32_t)stg_n * BW_STRIDE + (stg_g * 16 + 2 * p) * 2;
                    *(uint32_t*)(nb + o)          = ph;
                    *(uint32_t*)(nb + 20480u + o) = pl;
                }
            }
            __syncthreads();
        }

        // ---- tanh-jet epilogue: acc -> new state (bf16 hi/lo) ----
        const float* bp = bl[layer];
        const int srcU = lane & 3;               // channel-0 row lane
        const int srcG = (lane - 16) & 31;       // channel-4 offset lane
        const int ch   = lane >> 2;
        #pragma unroll
        for (int mt = 0; mt < 2; mt++) {
            #pragma unroll
            for (int nt = 0; nt < 8; nt++) {
                float* a = acc[mt][nt];
                const int jc = warpN * 64 + nt * 8 + 2 * (lane & 3);
                const float bj0 = __ldg(bp + jc);
                const float bj1 = __ldg(bp + jc + 1);
                #pragma unroll
                for (int grp = 0; grp < 2; grp++) {
                    const float va = a[grp * 2], vb = a[grp * 2 + 1];
                    const float ua = __shfl_sync(0xffffffffu, va, srcU);
                    const float ub = __shfl_sync(0xffffffffu, vb, srcU);
                    const float ga = __shfl_sync(0xffffffffu, va, srcG);
                    const float gb = __shfl_sync(0xffffffffu, vb, srcG);
                    const float ta = tanhf(ua + bj0);
                    const float tb = tanhf(ub + bj1);
                    const float da = 1.f - ta * ta, db = 1.f - tb * tb;
                    const float ma = -2.f * ta * da, mb = -2.f * tb * db;
                    const float oa = (ch == 0) ? ta : (ch <= 4) ? da * va
                                    : da * va + ma * ga * ga;
                    const float ob = (ch == 0) ? tb : (ch <= 4) ? db * vb
                                    : db * vb + mb * gb * gb;
                    uint32_t ph, pl;
                    split2(oa, ob, ph, pl);
                    const uint32_t r = (uint32_t)(warpM * 32 + mt * 16 + (lane >> 2) + grp * 8);
                    *(uint32_t*)(sm + OFF_SHI + r * SH_STRIDE + jc * 2) = ph;
                    *(uint32_t*)(sm + OFF_SLO + r * SH_STRIDE + jc * 2) = pl;
                }
            }
        }
        __syncthreads();
    }

    // ---- output layer 256->2 + divergence: warp w handles sample w ----
    {
        const int s  = w;                 // 0..15
        const int gs = s0 + s;
        float p0[8], p1[8];
        #pragma unroll
        for (int c = 0; c < 8; c++) { p0[c] = 0.f; p1[c] = 0.f; }
        #pragma unroll
        for (int it = 0; it < 4; it++) {
            const int jp = lane + it * 32;        // col pair index
            const int j  = 2 * jp;
            const float wo00 = __ldg(Wo + j * 2 + 0);
            const float wo01 = __ldg(Wo + j * 2 + 1);
            const float wo10 = __ldg(Wo + (j + 1) * 2 + 0);
            const float wo11 = __ldg(Wo + (j + 1) * 2 + 1);
            #pragma unroll
            for (int c = 0; c < 8; c++) {
                const uint32_t r = (uint32_t)(s * 8 + c);
                uint32_t uh = *(const uint32_t*)(sm + OFF_SHI + r * SH_STRIDE + j * 2);
                uint32_t ul = *(const uint32_t*)(sm + OFF_SLO + r * SH_STRIDE + j * 2);
                float v0 = bflo(uh) + bflo(ul);
                float v1 = bfhi(uh) + bfhi(ul);
                p0[c] = fmaf(v0, wo00, fmaf(v1, wo10, p0[c]));
                p1[c] = fmaf(v0, wo01, fmaf(v1, wo11, p1[c]));
            }
        }
        #pragma unroll
        for (int off = 16; off > 0; off >>= 1) {
            #pragma unroll
            for (int c = 0; c < 8; c++) {
                p0[c] += __shfl_xor_sync(0xffffffffu, p0[c], off);
                p1[c] += __shfl_xor_sync(0xffffffffu, p1[c], off);
            }
        }
        if (lane == 0 && gs < B) {
            float cc  = p0[0] + __ldg(bo + 0);
            float Fi  = p1[0] + __ldg(bo + 1);
            float ct  = p0[4];
            float cg0 = p0[1], cg1 = p0[2], cg2 = p0[3];
            float fg0 = p1[1], fg1 = p1[2], fg2 = p1[3];
            float clap = p0[5] + p0[6] + p0[7];
            float flap = p1[5] + p1[6] + p1[7];
            float jdiv = -clap
                       - (cg0 * fg0 + cg1 * fg1 + cg2 * fg2 + cc * flap)
                       + 0.1f * (cg0 + cg1 + cg2);
            out[gs]                 = cc;
            out[B + gs]             = ct;
            out[2 * B + gs * 3 + 0] = cg0;
            out[2 * B + gs * 3 + 1] = cg1;
            out[2 * B + gs * 3 + 2] = cg2;
            out[5 * B + gs]         = Fi;
            out[6 * B + gs * 3 + 0] = fg0;
            out[6 * B + gs * 3 + 1] = fg1;
            out[6 * B + gs * 3 + 2] = fg2;
            out[9 * B + gs]         = flap;
            out[10 * B + gs]        = jdiv;
        }
    }
}

extern "C" void kernel_launch(void* const* d_in, const int* in_sizes, int n_in,
                              void* d_out, int out_size)
{
    const float* x  = (const float*)d_in[0];
    const float* W0 = (const float*)d_in[1];
    const float* b0 = (const float*)d_in[2];
    const float* W1 = (const float*)d_in[3];
    const float* b1 = (const float*)d_in[4];
    const float* W2 = (const float*)d_in[5];
    const float* b2 = (const float*)d_in[6];
    const float* W3 = (const float*)d_in[7];
    const float* b3 = (const float*)d_in[8];
    const float* Wo = (const float*)d_in[9];
    const float* bo = (const float*)d_in[10];
    float* out = (float*)d_out;

    const int B = in_sizes[0] / 4;

    cudaFuncSetAttribute(jet_mma_kernel,
                         cudaFuncAttributeMaxDynamicSharedMemorySize, SMEM_BYTES);

    dim3 grid((B + SPC - 1) / SPC);
    jet_mma_kernel<<<grid, 512, SMEM_BYTES>>>(x, W0, b0, W1, b1, W2, b2, W3, b3,
                                              Wo, bo, out, B);
}